// round 6
// baseline (speedup 1.0000x reference)
#include <cuda_runtime.h>
#include <cuda_bf16.h>

// ResidualAverageBlock:
//   s[32] = sum_n w_n * x_n ;  sw = sum_n w_n
//   h     = relu( (s @ W_in^T) / sw )          [128]
//   x_    = h @ W_out^T                        [32]   (second average collapses: batch=1)
//   out   = x + x_  (broadcast over N rows)
//
// Three graph-capturable launches; scratch in __device__ globals (no allocation).

#define BLOCKS_A 296
#define TPB_A    512
#define WARPS_A  (TPB_A / 32)            // 16 warps/block
#define TOTAL_WARPS (BLOCKS_A * WARPS_A) // 4736

__device__ float g_part[33 * BLOCKS_A];  // layout [c][b] : g_part[c*BLOCKS_A + b]
__device__ float g_res[32];              // broadcast vector x_

// ---------------------------------------------------------------------------
// Pass 1: column-wise weighted reduce. Lane l owns column l. Each warp reads a
// contiguous chunk of rows (one 128B line per row, fully coalesced).
// Deterministic: fixed per-warp chunks, fixed shared-memory tree, no atomics.
// ---------------------------------------------------------------------------
__global__ __launch_bounds__(TPB_A, 2)
void reduce_kernel(const float* __restrict__ x, const float* __restrict__ w, int N)
{
    const int lane = threadIdx.x & 31;
    const int warp = threadIdx.x >> 5;
    const int gw   = blockIdx.x * WARPS_A + warp;

    const int R  = (N + TOTAL_WARPS - 1) / TOTAL_WARPS;   // rows per warp
    int row      = gw * R;
    const int r1 = min(row + R, N);

    float acc = 0.f, accw = 0.f;

    // unroll-4 over contiguous rows: 4 independent 128B row loads in flight
    for (; row + 4 <= r1; row += 4) {
        float w0 = __ldg(&w[row+0]);
        float w1 = __ldg(&w[row+1]);
        float w2 = __ldg(&w[row+2]);
        float w3 = __ldg(&w[row+3]);
        float x0 = __ldg(&x[(row+0)*32 + lane]);
        float x1 = __ldg(&x[(row+1)*32 + lane]);
        float x2 = __ldg(&x[(row+2)*32 + lane]);
        float x3 = __ldg(&x[(row+3)*32 + lane]);
        acc  = fmaf(w0, x0, acc);
        acc  = fmaf(w1, x1, acc);
        acc  = fmaf(w2, x2, acc);
        acc  = fmaf(w3, x3, acc);
        accw += (w0 + w1) + (w2 + w3);
    }
    for (; row < r1; ++row) {
        float wv = __ldg(&w[row]);
        acc  = fmaf(wv, __ldg(&x[row*32 + lane]), acc);
        accw += wv;
    }

    __shared__ float sh[WARPS_A][33];
    sh[warp][lane] = acc;
    if (lane == 0) sh[warp][32] = accw;   // identical in all lanes; take lane 0
    __syncthreads();

    if (threadIdx.x < 33) {
        float s = 0.f;
        #pragma unroll
        for (int q = 0; q < WARPS_A; ++q) s += sh[q][threadIdx.x];
        g_part[threadIdx.x * BLOCKS_A + blockIdx.x] = s;
    }
}

// ---------------------------------------------------------------------------
// Pass 2 (tiny, 1 block): finish reduce, compute h = relu(s@Win^T/sw),
// x_ = h@Wout^T. Deterministic strided partial sums.
// ---------------------------------------------------------------------------
__global__ void mid_kernel(const float* __restrict__ Win,   // [128,32] row-major
                           const float* __restrict__ Wout)  // [32,128] row-major
{
    __shared__ float red[33][8];
    __shared__ float s[33];
    __shared__ float h[128];

    const int t = threadIdx.x;   // 288 threads

    if (t < 264) {                       // 33 columns x 8 sub-reducers
        int c = t >> 3, k = t & 7;
        float a = 0.f;
        #pragma unroll 4
        for (int b = k; b < BLOCKS_A; b += 8)
            a += g_part[c * BLOCKS_A + b];
        red[c][k] = a;
    }
    __syncthreads();

    if (t < 33) {
        float a = 0.f;
        #pragma unroll
        for (int k = 0; k < 8; ++k) a += red[t][k];
        s[t] = a;
    }
    __syncthreads();

    if (t < 128) {
        float inv = 1.f / s[32];
        float d = 0.f;
        #pragma unroll
        for (int i = 0; i < 32; ++i)
            d = fmaf(s[i], Win[t * 32 + i], d);
        h[t] = fmaxf(d * inv, 0.f);
    }
    __syncthreads();

    if (t < 32) {
        float d = 0.f;
        #pragma unroll
        for (int j = 0; j < 128; ++j)
            d = fmaf(h[j], Wout[t * 128 + j], d);
        g_res[t] = d;
    }
}

// ---------------------------------------------------------------------------
// Pass 3: out = x + broadcast(x_). float4 streaming, grid-stride.
// ---------------------------------------------------------------------------
__global__ __launch_bounds__(256)
void add_kernel(const float* __restrict__ x, float* __restrict__ out, int n4)
{
    __shared__ float4 r4[8];
    if (threadIdx.x < 8)
        r4[threadIdx.x] = reinterpret_cast<const float4*>(g_res)[threadIdx.x];
    __syncthreads();

    const float4* __restrict__ x4 = reinterpret_cast<const float4*>(x);
    float4* __restrict__ o4       = reinterpret_cast<float4*>(out);

    int idx    = blockIdx.x * blockDim.x + threadIdx.x;
    int stride = gridDim.x * blockDim.x;

    #pragma unroll 4
    for (; idx < n4; idx += stride) {
        float4 v = x4[idx];
        float4 r = r4[idx & 7];
        v.x += r.x; v.y += r.y; v.z += r.z; v.w += r.w;
        o4[idx] = v;
    }
}

// ---------------------------------------------------------------------------
extern "C" void kernel_launch(void* const* d_in, const int* in_sizes, int n_in,
                              void* d_out, int out_size)
{
    const float* x    = (const float*)d_in[0];   // [N,32]
    const float* w    = (const float*)d_in[1];   // [N,1]
    const float* Win  = (const float*)d_in[2];   // [128,32]
    const float* Wout = (const float*)d_in[3];   // [32,128]
    float* out        = (float*)d_out;           // [N,32]

    const int N = in_sizes[1];                   // 1,000,000

    reduce_kernel<<<BLOCKS_A, TPB_A>>>(x, w, N);
    mid_kernel<<<1, 288>>>(Win, Wout);
    add_kernel<<<1184, 256>>>(x, out, N * 8);    // N*32/4 float4 elements
}

// round 8
// speedup vs baseline: 1.0273x; 1.0273x over previous
#include <cuda_runtime.h>
#include <cuda_bf16.h>

// ResidualAverageBlock, fused single persistent kernel:
//   Phase A: s[32] = sum_n w_n * x_n ; sw = sum_n w_n   (per-block partials)
//   grid-barrier (atomic arrive + monotone release, replay-safe)
//   Phase B (last-arriving block): h = relu((s@Win^T)/sw); x_ = h@Wout^T
//   Phase C (all blocks): out = x + broadcast(x_)

#define BLOCKS_A 296
#define TPB_A    512
#define WARPS_A  (TPB_A / 32)             // 16
#define TOTAL_WARPS (BLOCKS_A * WARPS_A)  // 4736

__device__ float g_part[33 * BLOCKS_A];   // [c][b]
__device__ float g_res[32];
__device__ int   g_arrive  = 0;           // reset by last block each run
__device__ int   g_release = 0;           // monotone across graph replays

__global__ __launch_bounds__(TPB_A, 2)
void fused_kernel(const float* __restrict__ x, const float* __restrict__ w,
                  const float* __restrict__ Win, const float* __restrict__ Wout,
                  float* __restrict__ out, int N)
{
    const int tid  = threadIdx.x;
    const int lane = tid & 31;
    const int warp = tid >> 5;
    const int sub  = lane & 7;     // column group: cols 4*sub .. 4*sub+3
    const int rg   = lane >> 3;    // row offset within 4-row group

    __shared__ float4 sh4[WARPS_A][8];
    __shared__ float  shw[WARPS_A];
    __shared__ float  red[33][8];
    __shared__ float  s_[33];
    __shared__ float  h_[128];
    __shared__ float4 r4s[8];
    __shared__ int    sh_last, sh_r0;

    // ---------------- Phase A: weighted column reduce ----------------
    {
        const float4* __restrict__ x4 = reinterpret_cast<const float4*>(x);
        const int gw = blockIdx.x * WARPS_A + warp;
        const int R  = (N + TOTAL_WARPS - 1) / TOTAL_WARPS;   // 212
        int row      = gw * R;
        const int r1 = min(row + R, N);

        float4 acc = make_float4(0.f, 0.f, 0.f, 0.f);
        float  accw = 0.f;

        // one LDG.128 per warp covers 4 rows; unroll 4 -> 16 rows/iter, 2KB/warp in flight
        for (; row + 16 <= r1; row += 16) {
            #pragma unroll
            for (int u = 0; u < 4; ++u) {
                int r = row + rg + (u << 2);
                float  wv = __ldg(&w[r]);
                float4 xv = __ldg(&x4[r * 8 + sub]);
                acc.x = fmaf(wv, xv.x, acc.x);
                acc.y = fmaf(wv, xv.y, acc.y);
                acc.z = fmaf(wv, xv.z, acc.z);
                acc.w = fmaf(wv, xv.w, acc.w);
                accw += wv;
            }
        }
        if (row < r1) {
            #pragma unroll
            for (int u = 0; u < 4; ++u) {
                int r = row + rg + (u << 2);
                if (r < r1) {
                    float  wv = __ldg(&w[r]);
                    float4 xv = __ldg(&x4[r * 8 + sub]);
                    acc.x = fmaf(wv, xv.x, acc.x);
                    acc.y = fmaf(wv, xv.y, acc.y);
                    acc.z = fmaf(wv, xv.z, acc.z);
                    acc.w = fmaf(wv, xv.w, acc.w);
                    accw += wv;
                }
            }
        }

        // reduce over rg (lanes differing in bits 3,4): each thread's rows are distinct,
        // duplicated only across sub -> accw needs NO correction.
        #pragma unroll
        for (int off = 8; off < 32; off <<= 1) {
            acc.x += __shfl_xor_sync(0xFFFFFFFFu, acc.x, off);
            acc.y += __shfl_xor_sync(0xFFFFFFFFu, acc.y, off);
            acc.z += __shfl_xor_sync(0xFFFFFFFFu, acc.z, off);
            acc.w += __shfl_xor_sync(0xFFFFFFFFu, acc.w, off);
            accw  += __shfl_xor_sync(0xFFFFFFFFu, accw,  off);
        }
        if (lane < 8)  sh4[warp][lane] = acc;
        if (lane == 0) shw[warp] = accw;
    }
    __syncthreads();

    if (tid < 32) {
        float v = 0.f;
        #pragma unroll
        for (int q = 0; q < WARPS_A; ++q)
            v += reinterpret_cast<const float*>(&sh4[q][tid >> 2])[tid & 3];
        g_part[tid * BLOCKS_A + blockIdx.x] = v;
    } else if (tid == 32) {
        float v = 0.f;
        #pragma unroll
        for (int q = 0; q < WARPS_A; ++q) v += shw[q];
        g_part[32 * BLOCKS_A + blockIdx.x] = v;
    }
    if (tid < 33) __threadfence();     // push g_part to L2 before arriving
    __syncthreads();

    // ---------------- grid barrier (replay-safe) ----------------
    if (tid == 0) {
        sh_r0 = *(volatile int*)&g_release;
        __threadfence();
        int t = atomicAdd(&g_arrive, 1);
        sh_last = (t == BLOCKS_A - 1);
    }
    __syncthreads();

    if (sh_last) {
        // ---------------- Phase B: finish reduce + tiny MLP ----------------
        if (tid < 264) {                       // 33 cols x 8 sub-reducers
            int c = tid >> 3, k = tid & 7;
            float a = 0.f;
            #pragma unroll 4
            for (int b = k; b < BLOCKS_A; b += 8)
                a += __ldcg(&g_part[c * BLOCKS_A + b]);
            red[c][k] = a;
        }
        __syncthreads();
        if (tid < 33) {
            float a = 0.f;
            #pragma unroll
            for (int k = 0; k < 8; ++k) a += red[tid][k];
            s_[tid] = a;
        }
        __syncthreads();
        if (tid < 128) {
            float inv = 1.f / s_[32];
            float d = 0.f;
            #pragma unroll
            for (int i = 0; i < 32; ++i) d = fmaf(s_[i], Win[tid * 32 + i], d);
            h_[tid] = fmaxf(d * inv, 0.f);
        }
        __syncthreads();
        if (tid < 32) {
            float d = 0.f;
            #pragma unroll
            for (int j = 0; j < 128; ++j) d = fmaf(h_[j], Wout[tid * 128 + j], d);
            g_res[tid] = d;
            __threadfence();
        }
        __syncthreads();
        if (tid == 0) {
            g_arrive = 0;                      // reset for next graph replay
            __threadfence();
            atomicAdd(&g_release, 1);          // monotone release
        }
    } else {
        if (tid == 0) {
            while (*(volatile int*)&g_release == sh_r0) __nanosleep(64);
        }
        __syncthreads();
        __threadfence();
    }

    // ---------------- Phase C: out = x + broadcast(x_) ----------------
    if (tid < 8) r4s[tid] = __ldcg(reinterpret_cast<const float4*>(g_res) + tid);
    __syncthreads();

    {
        const float4* __restrict__ xr = reinterpret_cast<const float4*>(x);
        float4* __restrict__ ow       = reinterpret_cast<float4*>(out);
        const int n4    = N * 8;
        const int chunk = (n4 + BLOCKS_A - 1) / BLOCKS_A;
        const int end   = min((blockIdx.x + 1) * chunk, n4);

        #pragma unroll 4
        for (int i = blockIdx.x * chunk + tid; i < end; i += TPB_A) {
            float4 v = xr[i];
            float4 r = r4s[i & 7];
            v.x += r.x; v.y += r.y; v.z += r.z; v.w += r.w;
            ow[i] = v;
        }
    }
}

extern "C" void kernel_launch(void* const* d_in, const int* in_sizes, int n_in,
                              void* d_out, int out_size)
{
    const float* x    = (const float*)d_in[0];   // [N,32]
    const float* w    = (const float*)d_in[1];   // [N,1]
    const float* Win  = (const float*)d_in[2];   // [128,32]
    const float* Wout = (const float*)d_in[3];   // [32,128]
    float* out        = (float*)d_out;           // [N,32]

    const int N = in_sizes[1];                   // 1,000,000

    fused_kernel<<<BLOCKS_A, TPB_A>>>(x, w, Win, Wout, out, N);
}